// round 16
// baseline (speedup 1.0000x reference)
#include <cuda_runtime.h>

#define REPS 1e-4f
#define GYP 148
#define NBLK_PROJ (4 * GYP)

// Scratch (no allocations allowed). Zero-init at load; last k_proj block
// resets g_M/g_cnt after consuming, so graph replays see clean state.
__device__ float    g_M[25 * 32];  // each accumulator on its own 128B line
__device__ unsigned g_cnt;
__device__ float    g_H[5 * 2048]; // H = A5 @ W2, produced by last proj block

__device__ __forceinline__ float4 ldcg4(const float* p) {
    float4 v;
    asm volatile("ld.global.cg.v4.f32 {%0,%1,%2,%3}, [%4];"
                 : "=f"(v.x), "=f"(v.y), "=f"(v.z), "=f"(v.w) : "l"(p));
    return v;
}
__device__ __forceinline__ float fsqrt_fast(float x) { return x * __frsqrt_rn(x); }

// ---------------------------------------------------------------------------
// K1 — Round-4 29.6us body; ONLY change: X loads via ld.global.cg (L2-only,
// no L1 line allocation — X is pure streaming, zero L1 reuse; frees L1 fill
// bandwidth for the sW1 broadcast LDS path).
// t[j][a] = sum_i W1[i,a]*X[i,j]; fold M[a][b] += t[j][a]*W1[j,b] once.
// Block: 256 thr, 1024-col tile (4 cols/thread), contiguous row band,
// W1 staged in shared as scalars, 4-row batched loads, 4 blocks/SM.
// Last block: thread 0 runs fast-math 5x5 Jacobi; 256 threads emit H=A5@W2.
// ---------------------------------------------------------------------------
__global__ __launch_bounds__(256, 4) void k_proj(const float* __restrict__ X,
                                                 const float* __restrict__ W1,
                                                 const float* __restrict__ W2) {
    const int tid = threadIdx.x;
    const int j0  = blockIdx.x * 1024 + tid * 4;
    const int r0  = (blockIdx.y * 4096) / GYP;
    const int r1  = ((blockIdx.y + 1) * 4096) / GYP;
    const int R   = r1 - r0;                      // 27 or 28

    __shared__ float sW1[28 * 5];
    __shared__ float sM[8][25];
    __shared__ float sA5[25];
    __shared__ bool  sLast;
    if (tid < R * 5) sW1[tid] = W1[r0 * 5 + tid];
    __syncthreads();

    float tacc[4][5];
#pragma unroll
    for (int cc = 0; cc < 4; cc++)
#pragma unroll
        for (int a = 0; a < 5; a++) tacc[cc][a] = 0.f;

    const float* Xb = X + (size_t)r0 * 4096 + j0;
    int r = 0;
    for (; r + 4 <= R; r += 4) {
        const float4 x0 = ldcg4(Xb + (size_t)(r + 0) * 4096);
        const float4 x1 = ldcg4(Xb + (size_t)(r + 1) * 4096);
        const float4 x2 = ldcg4(Xb + (size_t)(r + 2) * 4096);
        const float4 x3 = ldcg4(Xb + (size_t)(r + 3) * 4096);
        const float4 xs[4] = {x0, x1, x2, x3};
#pragma unroll
        for (int k = 0; k < 4; k++) {
            const float xv[4] = {xs[k].x, xs[k].y, xs[k].z, xs[k].w};
            float w[5];
#pragma unroll
            for (int a = 0; a < 5; a++) w[a] = sW1[(r + k) * 5 + a];
#pragma unroll
            for (int cc = 0; cc < 4; cc++)
#pragma unroll
                for (int a = 0; a < 5; a++) tacc[cc][a] += xv[cc] * w[a];
        }
    }
    for (; r < R; r++) {
        const float4 x = ldcg4(Xb + (size_t)r * 4096);
        const float xv[4] = {x.x, x.y, x.z, x.w};
        float w[5];
#pragma unroll
        for (int a = 0; a < 5; a++) w[a] = sW1[r * 5 + a];
#pragma unroll
        for (int cc = 0; cc < 4; cc++)
#pragma unroll
            for (int a = 0; a < 5; a++) tacc[cc][a] += xv[cc] * w[a];
    }

    // Fold with W1[j,b] once per thread
    float mp[5][5];
#pragma unroll
    for (int a = 0; a < 5; a++)
#pragma unroll
        for (int b = 0; b < 5; b++) mp[a][b] = 0.f;
#pragma unroll
    for (int cc = 0; cc < 4; cc++) {
        float w1j[5];
#pragma unroll
        for (int b = 0; b < 5; b++) w1j[b] = __ldg(W1 + (j0 + cc) * 5 + b);
#pragma unroll
        for (int a = 0; a < 5; a++)
#pragma unroll
            for (int b = 0; b < 5; b++) mp[a][b] += tacc[cc][a] * w1j[b];
    }

    // Block reduce 25 values -> 25 padded global atomics
    const int lane = tid & 31, warp = tid >> 5;
#pragma unroll
    for (int e = 0; e < 25; e++) {
        float v = mp[e / 5][e % 5];
#pragma unroll
        for (int o = 16; o > 0; o >>= 1) v += __shfl_down_sync(0xffffffffu, v, o);
        if (lane == 0) sM[warp][e] = v;
    }
    __syncthreads();
    if (tid < 25) {
        float v = 0.f;
#pragma unroll
        for (int wq = 0; wq < 8; wq++) v += sM[wq][tid];
        atomicAdd(&g_M[tid * 32], v);
    }
    if (tid == 0) {
        __threadfence();
        sLast = (atomicAdd(&g_cnt, 1u) == (unsigned)NBLK_PROJ - 1u);
    }
    __syncthreads();
    if (!sLast) return;

    // ---- Last block. Thread 0: B = M*M^T ; fast Jacobi ; A5 -> shared ----
    if (tid == 0) {
        float m[5][5], b[5][5], u[5][5];
#pragma unroll
        for (int a = 0; a < 5; a++)
#pragma unroll
            for (int c = 0; c < 5; c++) m[a][c] = __ldcg(&g_M[(a * 5 + c) * 32]);

        float tr = 0.f;
#pragma unroll
        for (int a = 0; a < 5; a++)
#pragma unroll
            for (int c = 0; c < 5; c++) {
                float s = 0.f;
#pragma unroll
                for (int k = 0; k < 5; k++) s += m[a][k] * m[c][k];
                b[a][c] = s;
                u[a][c] = (a == c) ? 1.f : 0.f;
                if (a == c) tr += s;
            }
        const float skip_tol = 1e-7f * tr;

#pragma unroll
        for (int sweep = 0; sweep < 5; sweep++) {
#pragma unroll
            for (int p = 0; p < 4; p++) {
#pragma unroll
                for (int q = p + 1; q < 5; q++) {
                    const float apq = b[p][q];
                    if (fabsf(apq) > skip_tol) {
                        const float tau = __fdividef(b[q][q] - b[p][p], 2.f * apq);
                        const float h   = fsqrt_fast(1.f + tau * tau);
                        const float t   = copysignf(__fdividef(1.f, fabsf(tau) + h), tau);
                        const float c   = __frsqrt_rn(1.f + t * t);
                        const float s   = t * c;
#pragma unroll
                        for (int k = 0; k < 5; k++) {
                            const float bkp = b[k][p], bkq = b[k][q];
                            b[k][p] = c * bkp - s * bkq;
                            b[k][q] = s * bkp + c * bkq;
                        }
#pragma unroll
                        for (int k = 0; k < 5; k++) {
                            const float bpk = b[p][k], bqk = b[q][k];
                            b[p][k] = c * bpk - s * bqk;
                            b[q][k] = s * bpk + c * bqk;
                            const float ukp = u[k][p], ukq = u[k][q];
                            u[k][p] = c * ukp - s * ukq;
                            u[k][q] = s * ukp + c * ukq;
                        }
                    }
                }
            }
        }

        float f[5];
#pragma unroll
        for (int d = 0; d < 5; d++) {
            const float lam = fmaxf(b[d][d], 0.f);
            f[d] = fmaxf(sqrtf(lam), REPS) - REPS;
        }
#pragma unroll
        for (int a = 0; a < 5; a++)
#pragma unroll
            for (int c = 0; c < 5; c++) {
                float s = 0.f;
#pragma unroll
                for (int d = 0; d < 5; d++) s += u[a][d] * f[d] * u[c][d];
                sA5[a * 5 + c] = s;
            }

        // Reset scratch for the next graph replay
#pragma unroll
        for (int e = 0; e < 25; e++) g_M[e * 32] = 0.f;
        g_cnt = 0u;
    }
    __syncthreads();

    // ---- All 256 threads: H[a][j] = sum_b A5[a][b] * W2[b][j] -> g_H ----
    float a5[5][5];
#pragma unroll
    for (int a = 0; a < 5; a++)
#pragma unroll
        for (int c = 0; c < 5; c++) a5[a][c] = sA5[a * 5 + c];
#pragma unroll
    for (int k = 0; k < 8; k++) {
        const int j = tid + 256 * k;
        float w2j[5];
#pragma unroll
        for (int b2 = 0; b2 < 5; b2++) w2j[b2] = __ldg(W2 + b2 * 2048 + j);
#pragma unroll
        for (int a = 0; a < 5; a++) {
            float s = 0.f;
#pragma unroll
            for (int b2 = 0; b2 < 5; b2++) s += a5[a][b2] * w2j[b2];
            g_H[a * 2048 + j] = s;
        }
    }
}

// ---------------------------------------------------------------------------
// K2 — Round-4 29.6us k_out verbatim: z[i][j] = sum_a W2[a,i]*H[a,j] +
// EPS*(i==j). Prologue: 5 coalesced float4 loads of H (L2-resident). Row
// loop prefetch-pipelined; stores coalesced float4. Grid (2,296), 5/SM cap.
// ---------------------------------------------------------------------------
__global__ __launch_bounds__(256, 5) void k_out(const float* __restrict__ W2,
                                                float* __restrict__ out) {
    const int tid = threadIdx.x;
    const int j0  = blockIdx.x * 1024 + tid * 4;

    float4 h[5];
#pragma unroll
    for (int a = 0; a < 5; a++)
        h[a] = *reinterpret_cast<const float4*>(g_H + a * 2048 + j0);

    int i = blockIdx.y;
    float w[5];
#pragma unroll
    for (int a = 0; a < 5; a++) w[a] = __ldg(W2 + a * 2048 + i);

    while (true) {
        const int inx = i + 296;
        const bool more = (inx < 2048);
        float wn[5];
        if (more) {
#pragma unroll
            for (int a = 0; a < 5; a++) wn[a] = __ldg(W2 + a * 2048 + inx);
        }
        float4 v;
        v.x = w[0] * h[0].x; v.y = w[0] * h[0].y;
        v.z = w[0] * h[0].z; v.w = w[0] * h[0].w;
#pragma unroll
        for (int a = 1; a < 5; a++) {
            v.x += w[a] * h[a].x; v.y += w[a] * h[a].y;
            v.z += w[a] * h[a].z; v.w += w[a] * h[a].w;
        }
        const int d = i - j0;
        if ((unsigned)d < 4u) {
            if (d == 0) v.x += REPS;
            else if (d == 1) v.y += REPS;
            else if (d == 2) v.z += REPS;
            else v.w += REPS;
        }
        *reinterpret_cast<float4*>(out + (size_t)i * 2048 + j0) = v;
        if (!more) break;
        i = inx;
#pragma unroll
        for (int a = 0; a < 5; a++) w[a] = wn[a];
    }
}

// ---------------------------------------------------------------------------
extern "C" void kernel_launch(void* const* d_in, const int* in_sizes, int n_in,
                              void* d_out, int out_size) {
    const float* X  = (const float*)d_in[0];   // (1, 4096, 4096) f32
    const float* W1 = (const float*)d_in[1];   // (4096, 5) f32
    const float* W2 = (const float*)d_in[2];   // (5, 2048) f32
    float* out = (float*)d_out;                // (2048, 2048) f32

    k_proj<<<dim3(4, GYP), 256>>>(X, W1, W2);
    k_out <<<dim3(2, 296), 256>>>(W2, out);
}